// round 9
// baseline (speedup 1.0000x reference)
#include <cuda_runtime.h>
#include <cuda_fp16.h>
#include <cstdint>
#include <math.h>

#define BB   16
#define CIN  128
#define COUT 256
#define KK   9
#define HH   56
#define WW   56
#define HW   3136
#define KDIM (CIN*KK)   // 1152
#define HP   58         // padded H
#define WP2  64         // padded/pair row stride (u32 units)

// GEMM tiling (mma.sync fp16 path)
#define BM 128
#define BN 112          // 3136 = 28 * 112 ; covers exactly 2 image rows
#define BK 64           // fp16 K per mainloop chunk
#define NCHUNK (KDIM/BK) // 18

// ---------------- device scratch (no allocations allowed) ----------------
__device__ float g_ctx[BB*CIN];
__device__ float g_attn_sp[BB*KK];
__device__ float g_attn_in[BB*CIN];
__device__ float g_attn_out[BB*COUT];
__device__ __align__(16) __half g_dynA[(size_t)BB*COUT*KDIM];    // 9.4MB fp16
// pair-duplicated padded image: P[pc][hp][w] = (x16(hp,w), x16(hp,w+1))
__device__ __align__(16) uint32_t g_xp2[(size_t)BB*CIN*HP*WP2];  // 30.4MB

// ======================= helpers =====================
__device__ __forceinline__ uint32_t smem_u32(const void* p) {
    uint32_t a;
    asm("{ .reg .u64 t; cvta.to.shared.u64 t, %1; cvt.u32.u64 %0, t; }"
        : "=r"(a) : "l"(p));
    return a;
}
__device__ __forceinline__ void ldm_x4(uint32_t* r0, uint32_t* r1, uint32_t* r2,
                                       uint32_t* r3, uint32_t addr) {
    asm volatile("ldmatrix.sync.aligned.m8n8.x4.shared.b16 {%0,%1,%2,%3}, [%4];"
        : "=r"(*r0), "=r"(*r1), "=r"(*r2), "=r"(*r3) : "r"(addr));
}
__device__ __forceinline__ void ldm_x4t(uint32_t* r0, uint32_t* r1, uint32_t* r2,
                                        uint32_t* r3, uint32_t addr) {
    asm volatile("ldmatrix.sync.aligned.m8n8.x4.trans.shared.b16 {%0,%1,%2,%3}, [%4];"
        : "=r"(*r0), "=r"(*r1), "=r"(*r2), "=r"(*r3) : "r"(addr));
}
__device__ __forceinline__ void ldm_x2t(uint32_t* r, uint32_t addr) {
    asm volatile("ldmatrix.sync.aligned.m8n8.x2.trans.shared.b16 {%0,%1}, [%2];"
        : "=r"(r[0]), "=r"(r[1]) : "r"(addr));
}
__device__ __forceinline__ void mma16816(float* d, const uint32_t* a, const uint32_t* b) {
    asm volatile("mma.sync.aligned.m16n8k16.row.col.f32.f16.f16.f32 "
        "{%0,%1,%2,%3}, {%4,%5,%6,%7}, {%8,%9}, {%0,%1,%2,%3};"
        : "+f"(d[0]), "+f"(d[1]), "+f"(d[2]), "+f"(d[3])
        : "r"(a[0]), "r"(a[1]), "r"(a[2]), "r"(a[3]), "r"(b[0]), "r"(b[1]));
}
__device__ __forceinline__ void cp16(uint32_t dst, const void* src) {
    asm volatile("cp.async.cg.shared.global [%0], [%1], 16;"
        :: "r"(dst), "l"(src));
}
__device__ __forceinline__ void cp4(uint32_t dst, const void* src) {
    asm volatile("cp.async.ca.shared.global [%0], [%1], 4;"
        :: "r"(dst), "l"(src));
}
#define CP_COMMIT() asm volatile("cp.async.commit_group;" ::: "memory")
#define CP_WAIT0()  asm volatile("cp.async.wait_group 0;" ::: "memory")

// 128B-row smem tile, XOR swizzle on 16B columns (A tile, non-trans ldmatrix)
#define SWADDR(row, c16) ((uint32_t)((row) * 128 + (((c16) ^ ((row) & 7)) << 4)))

// ------- 1) fused: pad + fp16-pair image AND per-channel mean -------------
__global__ __launch_bounds__(256) void k_ctxpad(const float* __restrict__ x) {
    int pc = blockIdx.x;                     // b*CIN + ci
    const float* xc = x + (size_t)pc * HW;
    uint32_t* xp = g_xp2 + (size_t)pc * HP * WP2;
    float s = 0.f;
    for (int idx = threadIdx.x; idx < HP*WP2; idx += 256) {
        int hp = idx >> 6;          // /WP2
        int w  = idx & 63;
        float v0 = 0.f, v1 = 0.f;
        if (hp >= 1 && hp <= HH) {
            const float* row = xc + (hp - 1) * WW;
            if (w >= 1 && w <= WW)     { v0 = row[w - 1]; s += v0; }
            if (w + 1 >= 1 && w + 1 <= WW) v1 = row[w];
        }
        __half_raw h0 = __float2half_rn(v0);
        __half_raw h1 = __float2half_rn(v1);
        xp[idx] = (uint32_t)h0.x | ((uint32_t)h1.x << 16);
    }
    __shared__ float sm[256];
    sm[threadIdx.x] = s; __syncthreads();
    #pragma unroll
    for (int off = 128; off > 0; off >>= 1) {
        if (threadIdx.x < off) sm[threadIdx.x] += sm[threadIdx.x + off];
        __syncthreads();
    }
    if (threadIdx.x == 0) g_ctx[pc] = sm[0] * (1.0f / HW);
}

// ---------------- 2) small attention heads ----------------
__global__ void k_attn(const float* __restrict__ fsw, const float* __restrict__ fsb,
                       const float* __restrict__ fiw, const float* __restrict__ fib,
                       const float* __restrict__ fow, const float* __restrict__ fob) {
    int gw   = (blockIdx.x * blockDim.x + threadIdx.x) >> 5;
    int lane = threadIdx.x & 31;
    const int NS = BB*KK, NI = BB*CIN, NO = BB*COUT;
    if (gw >= NS + NI + NO) return;
    int b; const float* wrow; float bias; float* dst;
    if (gw < NS) {
        b = gw / KK; int r = gw % KK;
        wrow = fsw + r*CIN; bias = fsb[r]; dst = &g_attn_sp[gw];
    } else if (gw < NS + NI) {
        int g = gw - NS; b = g / CIN; int r = g % CIN;
        wrow = fiw + r*CIN; bias = fib[r]; dst = &g_attn_in[g];
    } else {
        int g = gw - NS - NI; b = g / COUT; int r = g % COUT;
        wrow = fow + r*CIN; bias = fob[r]; dst = &g_attn_out[g];
    }
    const float* ctx = g_ctx + b*CIN;
    float s = 0.f;
    #pragma unroll
    for (int j = lane; j < CIN; j += 32) s += ctx[j] * wrow[j];
    #pragma unroll
    for (int o = 16; o > 0; o >>= 1) s += __shfl_down_sync(0xffffffffu, s, o);
    if (lane == 0) *dst = 1.f / (1.f + expf(-(s + bias)));
}

// ------- 3) big-GEMM + sigmoid + 5-way multiply, smem-staged weights ------
#define CK     32
#define WROWB  144                 // bytes per smem row: 32 floats + 16B pad
#define DSTG   (256*WROWB)         // 36864 bytes per stage
#define DYN_SMEM (8192 + 2*DSTG)   // ctx (8KB) + 2 stages = 81920

__global__ __launch_bounds__(256) void k_dyn(const float* __restrict__ base_kernel,
                                             const float* __restrict__ fkw,
                                             const float* __restrict__ fkb) {
    extern __shared__ char dsm[];
    float* ctx_s = (float*)dsm;
    uint32_t sbase = smem_u32(dsm);
    int tid = threadIdx.x;
    for (int i = tid; i < BB*CIN; i += 256) ctx_s[i] = g_ctx[i];

    int r0 = blockIdx.x * 256;
    int r  = r0 + tid;

    auto loadW = [&](int c, uint32_t stg) {
        int k0 = c * CK;
        const float* src0 = fkw + (size_t)r0 * CIN + k0;
        #pragma unroll
        for (int cc = 0; cc < 8; cc++) {
            int i = cc * 256 + tid;
            int row  = i >> 3;
            int col4 = i & 7;
            cp16(sbase + 8192 + stg + row * WROWB + col4 * 16,
                 src0 + (size_t)row * CIN + col4 * 4);
        }
    };

    float acc[BB];
    #pragma unroll
    for (int b = 0; b < BB; b++) acc[b] = 0.f;

    loadW(0, 0);
    CP_COMMIT();
    __syncthreads();

    for (int c = 0; c < 4; c++) {
        uint32_t s_stg = (c & 1) ? DSTG : 0;
        uint32_t n_stg = (c & 1) ? 0 : DSTG;
        CP_WAIT0();
        __syncthreads();
        if (c < 3) { loadW(c + 1, n_stg); CP_COMMIT(); }

        const float4* wrow = (const float4*)(dsm + 8192 + s_stg + tid * WROWB);
        int k0 = c * CK;
        #pragma unroll
        for (int u = 0; u < 8; u++) {
            float4 w4 = wrow[u];
            #pragma unroll
            for (int b = 0; b < BB; b++) {
                const float* cb = ctx_s + b * CIN + k0 + u * 4;
                acc[b] += w4.x*cb[0] + w4.y*cb[1] + w4.z*cb[2] + w4.w*cb[3];
            }
        }
        __syncthreads();
    }

    int o   = r / KDIM;
    int rem = r - o*KDIM;
    int i   = rem / KK;
    int kk  = rem - i*KK;
    float bk = base_kernel[r];
    float fb = fkb[r];
    #pragma unroll
    for (int b = 0; b < BB; b++) {
        float sg = 1.f / (1.f + expf(-(acc[b] + fb)));
        float v  = bk * g_attn_out[b*COUT + o] * g_attn_in[b*CIN + i]
                      * g_attn_sp[b*KK + kk] * sg;
        g_dynA[(size_t)b * COUT * KDIM + r] = __float2half_rn(v);
    }
}

// ---- 4) tensor-core conv: 4 warps, warp tile 64x56, all-cp.async B -------
// Per stage: A 16KB (swizzled) | B 64x240B = 15360B; STG = 31744; 2 stages.
#define OFF_A    0
#define OFF_B    16384
#define BROWB    240
#define STG      31744
#define SMEM_BYTES (2*STG)   // 63488

__global__ __launch_bounds__(128, 3) void k_conv_mma(const float* __restrict__ bias,
                                                     float* __restrict__ out) {
    extern __shared__ char smem[];
    uint32_t sbase = smem_u32(smem);
    int tid  = threadIdx.x;
    int wid  = tid >> 5;
    int lane = tid & 31;

    int b  = blockIdx.z;
    int m0 = blockIdx.y * BM;
    int n0 = blockIdx.x * BN;

    const __half* A = g_dynA + (size_t)(b*COUT + m0) * KDIM;
    const uint32_t* Xp = g_xp2 + (size_t)b * CIN * HP * WP2;

    // warp tile: 64(m) x 56(n) -- 2 M-warps x 2 N-warps
    int warp_m = (wid & 1) * 64;
    int warp_n = (wid >> 1) * 56;

    // per-lane A ldmatrix addressing (swizzled, non-trans)
    int amat  = lane >> 3;
    int arow0 = warp_m + (amat & 1) * 8 + (lane & 7);
    int ac16  = amat >> 1;
    // per-lane B trans-ldmatrix addressing ([k][n] K-major rows)
    int bg    = lane >> 3;                      // 0..3
    int bkrow = ((bg & 1) << 3) + (lane & 7);   // k within 16-step
    int bnx4  = warp_n + ((bg >> 1) << 3);      // + p*16 per pair
    int bkrow2 = (((lane >> 3) & 1) << 3) + (lane & 7);  // for x2

    // B gather mapping: kc = tid&63 (k in chunk), h_local = tid>>6 (0..1)
    int kc = tid & 63;
    int h_local = tid >> 6;
    int hbase = blockIdx.x * 2;

    float acc[4][7][4];
    #pragma unroll
    for (int t = 0; t < 4; t++)
        #pragma unroll
        for (int nt = 0; nt < 7; nt++)
            #pragma unroll
            for (int i = 0; i < 4; i++) acc[t][nt][i] = 0.f;

    auto loadA = [&](int kt, uint32_t stg_off) {
        int k0 = kt * BK;
        #pragma unroll
        for (int c = 0; c < 8; c++) {
            int idx = c * 128 + tid;       // 0..1023
            int row = idx >> 3;            // 0..127
            int c16 = idx & 7;
            size_t src = (size_t)row * KDIM + k0 + c16 * 8;
            cp16(sbase + stg_off + OFF_A + SWADDR(row, c16), A + src);
        }
    };
    auto loadB = [&](int kt, uint32_t stg_off) {
        int k  = kt * BK + kc;
        int ci = k / 9;
        int r9 = k - ci * 9;
        int kh = r9 / 3;
        int kw = r9 - kh * 3;
        const uint32_t* src = Xp + (size_t)(ci * HP + hbase + h_local + kh) * WP2
                                 + kw;
        uint32_t dst = sbase + stg_off + OFF_B + kc * BROWB + h_local * 112;
        #pragma unroll
        for (int p = 0; p < 28; p++) cp4(dst + 4*p, src + 2*p);
    };

    // ---- prologue: stage 0 = chunk 0 ----
    loadA(0, 0);
    loadB(0, 0);
    CP_COMMIT();

    for (int kt = 0; kt < NCHUNK; kt++) {
        uint32_t s_off = (kt & 1) ? STG : 0;
        uint32_t n_off = (kt & 1) ? 0 : STG;
        CP_WAIT0();
        __syncthreads();

        if (kt + 1 < NCHUNK) {
            loadA(kt + 1, n_off);
            loadB(kt + 1, n_off);
            CP_COMMIT();
        }

        // ---- compute: 4 k16-steps ----
        #pragma unroll
        for (int ks = 0; ks < 4; ks++) {
            uint32_t af[4][4], bf[7][2];
            #pragma unroll
            for (int t = 0; t < 4; t++) {
                uint32_t aoff = SWADDR(arow0 + t*16, ks*2 + ac16);
                ldm_x4(&af[t][0], &af[t][1], &af[t][2], &af[t][3],
                       sbase + s_off + OFF_A + aoff);
            }
            #pragma unroll
            for (int p = 0; p < 3; p++) {
                uint32_t boff = (uint32_t)((ks*16 + bkrow) * BROWB
                                           + (bnx4 + p*16) * 2);
                ldm_x4t(&bf[2*p][0], &bf[2*p][1], &bf[2*p+1][0], &bf[2*p+1][1],
                        sbase + s_off + OFF_B + boff);
            }
            {
                uint32_t boff = (uint32_t)((ks*16 + bkrow2) * BROWB
                                           + (warp_n + 48) * 2);
                ldm_x2t(bf[6], sbase + s_off + OFF_B + boff);
            }
            #pragma unroll
            for (int nt = 0; nt < 7; nt++)
                #pragma unroll
                for (int t = 0; t < 4; t++)
                    mma16816(acc[t][nt], af[t], bf[nt]);
        }
    }

    // ---- epilogue: D frag -> gmem with bias ----
    int r4 = lane >> 2;
    int c2 = (lane & 3) * 2;
    #pragma unroll
    for (int t = 0; t < 4; t++) {
        int or0 = m0 + warp_m + t*16 + r4;
        float bi0 = bias[or0];
        float bi1 = bias[or0 + 8];
        float* op0 = out + ((size_t)b * COUT + or0    ) * HW + n0 + warp_n + c2;
        float* op1 = out + ((size_t)b * COUT + or0 + 8) * HW + n0 + warp_n + c2;
        #pragma unroll
        for (int nt = 0; nt < 7; nt++) {
            float2 v0 = make_float2(acc[t][nt][0] + bi0, acc[t][nt][1] + bi0);
            float2 v1 = make_float2(acc[t][nt][2] + bi1, acc[t][nt][3] + bi1);
            *(float2*)(op0 + nt*8) = v0;
            *(float2*)(op1 + nt*8) = v1;
        }
    }
}

// ---------------- launch ----------------
extern "C" void kernel_launch(void* const* d_in, const int* in_sizes, int n_in,
                              void* d_out, int out_size) {
    const float* x    = (const float*)d_in[0];
    const float* bk   = (const float*)d_in[1];
    const float* bias = (const float*)d_in[2];
    const float* fsw  = (const float*)d_in[3];
    const float* fsb  = (const float*)d_in[4];
    const float* fiw  = (const float*)d_in[5];
    const float* fib  = (const float*)d_in[6];
    const float* fow  = (const float*)d_in[7];
    const float* fob  = (const float*)d_in[8];
    const float* fkw  = (const float*)d_in[9];
    const float* fkb  = (const float*)d_in[10];
    float* out = (float*)d_out;

    k_ctxpad<<<BB*CIN, 256>>>(x);

    int total_warps = BB * (KK + CIN + COUT);
    k_attn<<<(total_warps*32 + 255)/256, 256>>>(fsw, fsb, fiw, fib, fow, fob);

    cudaFuncSetAttribute(k_dyn, cudaFuncAttributeMaxDynamicSharedMemorySize,
                         DYN_SMEM);
    k_dyn<<<(COUT*KDIM)/256, 256, DYN_SMEM>>>(bk, fkw, fkb);

    cudaFuncSetAttribute(k_conv_mma, cudaFuncAttributeMaxDynamicSharedMemorySize,
                         SMEM_BYTES);
    dim3 grid(HW/BN, COUT/BM, BB);   // (28, 2, 16)
    k_conv_mma<<<grid, 128, SMEM_BYTES>>>(bias, out);
}

// round 10
// speedup vs baseline: 1.2531x; 1.2531x over previous
#include <cuda_runtime.h>
#include <cuda_fp16.h>
#include <cstdint>
#include <math.h>

#define BB   16
#define CIN  128
#define COUT 256
#define KK   9
#define HH   56
#define WW   56
#define HW   3136
#define KDIM (CIN*KK)   // 1152
#define HP   58         // padded H
#define WP2  64         // padded/pair row stride (u32 units)

// GEMM tiling (mma.sync fp16 conv path)
#define BM 128
#define BN 112          // 3136 = 28 * 112
#define BK 64
#define NCHUNK (KDIM/BK) // 18

// ---------------- device scratch (no allocations allowed) ----------------
__device__ float g_ctx[BB*CIN];
__device__ float g_attn_sp[BB*KK];
__device__ float g_attn_in[BB*CIN];
__device__ float g_attn_out[BB*COUT];
__device__ __align__(16) __half g_dynA[(size_t)BB*COUT*KDIM];    // 9.4MB fp16
// pair-duplicated padded image: P[pc][hp][w] = (x16(hp,w-1), x16(hp,w))
__device__ __align__(16) uint32_t g_xp2[(size_t)BB*CIN*HP*WP2];  // 30.4MB

// ======================= helpers =====================
__device__ __forceinline__ uint32_t smem_u32(const void* p) {
    uint32_t a;
    asm("{ .reg .u64 t; cvta.to.shared.u64 t, %1; cvt.u32.u64 %0, t; }"
        : "=r"(a) : "l"(p));
    return a;
}
__device__ __forceinline__ void ldm_x4(uint32_t* r0, uint32_t* r1, uint32_t* r2,
                                       uint32_t* r3, uint32_t addr) {
    asm volatile("ldmatrix.sync.aligned.m8n8.x4.shared.b16 {%0,%1,%2,%3}, [%4];"
        : "=r"(*r0), "=r"(*r1), "=r"(*r2), "=r"(*r3) : "r"(addr));
}
__device__ __forceinline__ void ldm_x4t(uint32_t* r0, uint32_t* r1, uint32_t* r2,
                                        uint32_t* r3, uint32_t addr) {
    asm volatile("ldmatrix.sync.aligned.m8n8.x4.trans.shared.b16 {%0,%1,%2,%3}, [%4];"
        : "=r"(*r0), "=r"(*r1), "=r"(*r2), "=r"(*r3) : "r"(addr));
}
__device__ __forceinline__ void ldm_x2t(uint32_t* r, uint32_t addr) {
    asm volatile("ldmatrix.sync.aligned.m8n8.x2.trans.shared.b16 {%0,%1}, [%2];"
        : "=r"(r[0]), "=r"(r[1]) : "r"(addr));
}
__device__ __forceinline__ void mma16816(float* d, const uint32_t* a, const uint32_t* b) {
    asm volatile("mma.sync.aligned.m16n8k16.row.col.f32.f16.f16.f32 "
        "{%0,%1,%2,%3}, {%4,%5,%6,%7}, {%8,%9}, {%0,%1,%2,%3};"
        : "+f"(d[0]), "+f"(d[1]), "+f"(d[2]), "+f"(d[3])
        : "r"(a[0]), "r"(a[1]), "r"(a[2]), "r"(a[3]), "r"(b[0]), "r"(b[1]));
}
__device__ __forceinline__ void cp16(uint32_t dst, const void* src) {
    asm volatile("cp.async.cg.shared.global [%0], [%1], 16;"
        :: "r"(dst), "l"(src));
}
#define CP_COMMIT() asm volatile("cp.async.commit_group;" ::: "memory")
#define CP_WAIT0()  asm volatile("cp.async.wait_group 0;" ::: "memory")

__device__ __forceinline__ uint32_t pack_h2(float lo, float hi) {
    __half2 h = __floats2half2_rn(lo, hi);
    return *reinterpret_cast<uint32_t*>(&h);
}

// 128B-row smem tile, XOR swizzle on 16B columns (conv A tile)
#define SWADDR(row, c16) ((uint32_t)((row) * 128 + (((c16) ^ ((row) & 7)) << 4)))
// 256B-row smem tile, XOR swizzle (k_dyn A/B tiles, 16 c16 units per row)
#define ASW(row, c16) ((uint32_t)((row) * 256 + (((((c16) ^ (row)) & 7) | ((c16) & 8)) << 4)))

// ------- 1) fused: pad + fp16-pair image AND per-channel mean -------------
__global__ __launch_bounds__(256) void k_ctxpad(const float* __restrict__ x) {
    int pc = blockIdx.x;                     // b*CIN + ci
    const float* xc = x + (size_t)pc * HW;
    uint32_t* xp = g_xp2 + (size_t)pc * HP * WP2;
    float s = 0.f;
    for (int idx = threadIdx.x; idx < HP*WP2; idx += 256) {
        int hp = idx >> 6;          // /WP2
        int w  = idx & 63;
        float v0 = 0.f, v1 = 0.f;
        if (hp >= 1 && hp <= HH) {
            const float* row = xc + (hp - 1) * WW;
            if (w >= 1 && w <= WW)     { v0 = row[w - 1]; s += v0; }
            if (w + 1 >= 1 && w + 1 <= WW) v1 = row[w];
        }
        xp[idx] = pack_h2(v0, v1);
    }
    __shared__ float sm[256];
    sm[threadIdx.x] = s; __syncthreads();
    #pragma unroll
    for (int off = 128; off > 0; off >>= 1) {
        if (threadIdx.x < off) sm[threadIdx.x] += sm[threadIdx.x + off];
        __syncthreads();
    }
    if (threadIdx.x == 0) g_ctx[pc] = sm[0] * (1.0f / HW);
}

// ---------------- 2) small attention heads ----------------
__global__ void k_attn(const float* __restrict__ fsw, const float* __restrict__ fsb,
                       const float* __restrict__ fiw, const float* __restrict__ fib,
                       const float* __restrict__ fow, const float* __restrict__ fob) {
    int gw   = (blockIdx.x * blockDim.x + threadIdx.x) >> 5;
    int lane = threadIdx.x & 31;
    const int NS = BB*KK, NI = BB*CIN, NO = BB*COUT;
    if (gw >= NS + NI + NO) return;
    int b; const float* wrow; float bias; float* dst;
    if (gw < NS) {
        b = gw / KK; int r = gw % KK;
        wrow = fsw + r*CIN; bias = fsb[r]; dst = &g_attn_sp[gw];
    } else if (gw < NS + NI) {
        int g = gw - NS; b = g / CIN; int r = g % CIN;
        wrow = fiw + r*CIN; bias = fib[r]; dst = &g_attn_in[g];
    } else {
        int g = gw - NS - NI; b = g / COUT; int r = g % COUT;
        wrow = fow + r*CIN; bias = fob[r]; dst = &g_attn_out[g];
    }
    const float* ctx = g_ctx + b*CIN;
    float s = 0.f;
    #pragma unroll
    for (int j = lane; j < CIN; j += 32) s += ctx[j] * wrow[j];
    #pragma unroll
    for (int o = 16; o > 0; o >>= 1) s += __shfl_down_sync(0xffffffffu, s, o);
    if (lane == 0) *dst = 1.f / (1.f + expf(-(s + bias)));
}

// ------- 3) tensorized big-GEMM + sigmoid + 5-way multiply ----------------
// logits[256 rows x 16 b] = fkw_tile[256x128] @ ctx^T ; fused epilogue -> g_dynA
// smem: A fp16 [256][128] swizzled 256B rows (64KB) | B(ctx) fp16 [16][128] (4KB)
#define DYN_OFF_B   65536
#define DYN_SMEM    69632

__global__ __launch_bounds__(256) void k_dyn_mma(const float* __restrict__ base_kernel,
                                                 const float* __restrict__ fkw,
                                                 const float* __restrict__ fkb) {
    extern __shared__ char dsm[];
    uint32_t sbase = smem_u32(dsm);
    int tid  = threadIdx.x;
    int wid  = tid >> 5;
    int lane = tid & 31;
    int r0   = blockIdx.x * 256;

    // ---- stage A: fkw fp32 -> fp16 swizzled smem (coalesced LDG.128 x2) ----
    #pragma unroll
    for (int i = 0; i < 16; i++) {
        int idx = i * 256 + tid;          // 0..4095
        int row = idx >> 4;               // 0..255
        int c16 = idx & 15;               // 16B unit (8 halves)
        const float* src = fkw + (size_t)(r0 + row) * CIN + c16 * 8;
        float4 a = *(const float4*)src;
        float4 b = *(const float4*)(src + 4);
        uint4 u;
        u.x = pack_h2(a.x, a.y); u.y = pack_h2(a.z, a.w);
        u.z = pack_h2(b.x, b.y); u.w = pack_h2(b.z, b.w);
        *(uint4*)(dsm + ASW(row, c16)) = u;
    }
    // ---- stage B: ctx fp32 -> fp16 swizzled smem ----
    {
        int n   = tid >> 4;               // 0..15
        int c16 = tid & 15;
        const float* src = g_ctx + n * CIN + c16 * 8;
        float4 a = *(const float4*)src;
        float4 b = *(const float4*)(src + 4);
        uint4 u;
        u.x = pack_h2(a.x, a.y); u.y = pack_h2(a.z, a.w);
        u.z = pack_h2(b.x, b.y); u.w = pack_h2(b.z, b.w);
        *(uint4*)(dsm + DYN_OFF_B + ASW(n, c16)) = u;
    }
    __syncthreads();

    // ---- MMA: warp handles 32 rows (2 m16 tiles) x 16 b ----
    int warp_m = wid * 32;
    int amat   = lane >> 3;
    int arow0  = warp_m + (amat & 1) * 8 + (lane & 7);
    int ac16   = amat >> 1;
    int brow   = ((lane >> 4) << 3) + (lane & 7);   // 0..15
    int bhalf  = (lane >> 3) & 1;

    float acc[2][2][4];
    #pragma unroll
    for (int t = 0; t < 2; t++)
        #pragma unroll
        for (int nf = 0; nf < 2; nf++)
            #pragma unroll
            for (int e = 0; e < 4; e++) acc[t][nf][e] = 0.f;

    #pragma unroll
    for (int ks = 0; ks < 8; ks++) {
        uint32_t af[2][4], bf[2][2];
        #pragma unroll
        for (int t = 0; t < 2; t++)
            ldm_x4(&af[t][0], &af[t][1], &af[t][2], &af[t][3],
                   sbase + ASW(arow0 + t*16, ks*2 + ac16));
        ldm_x4(&bf[0][0], &bf[0][1], &bf[1][0], &bf[1][1],
               sbase + DYN_OFF_B + ASW(brow, ks*2 + bhalf));
        #pragma unroll
        for (int t = 0; t < 2; t++)
            #pragma unroll
            for (int nf = 0; nf < 2; nf++)
                mma16816(acc[t][nf], af[t], bf[nf]);
    }

    // ---- fused epilogue: sigmoid + 5-way multiply -> g_dynA fp16 ----
    int r4 = lane >> 2;
    int c2 = (lane & 3) * 2;
    #pragma unroll
    for (int t = 0; t < 2; t++) {
        #pragma unroll
        for (int rh = 0; rh < 2; rh++) {
            int r   = r0 + warp_m + t*16 + rh*8 + r4;
            float bk = base_kernel[r];
            float fb = fkb[r];
            int o    = r / KDIM;
            int rem  = r - o * KDIM;
            int i    = rem / KK;
            int kk   = rem - i * KK;
            #pragma unroll
            for (int nf = 0; nf < 2; nf++) {
                #pragma unroll
                for (int par = 0; par < 2; par++) {
                    int b = nf*8 + c2 + par;
                    float z  = acc[t][nf][rh*2 + par] + fb;
                    float sg = 1.f / (1.f + expf(-z));
                    float v  = bk * g_attn_out[b*COUT + o] * g_attn_in[b*CIN + i]
                                  * g_attn_sp[b*KK + kk] * sg;
                    g_dynA[(size_t)b * COUT * KDIM + r] = __float2half_rn(v);
                }
            }
        }
    }
}

// ---- 4) tensor-core conv (R8 config): 8 warps, warp 32x56, K-major B -----
#define OFF_A    0
#define OFF_B    16384
#define BROWB    240
#define STG      31744
#define SMEM_BYTES (2*STG)   // 63488

__global__ __launch_bounds__(256, 2) void k_conv_mma(const float* __restrict__ bias,
                                                     float* __restrict__ out) {
    extern __shared__ char smem[];
    uint32_t sbase = smem_u32(smem);
    int tid  = threadIdx.x;
    int wid  = tid >> 5;
    int lane = tid & 31;

    int b  = blockIdx.z;
    int m0 = blockIdx.y * BM;
    int n0 = blockIdx.x * BN;

    const __half* A = g_dynA + (size_t)(b*COUT + m0) * KDIM;
    const uint32_t* Xp = g_xp2 + (size_t)b * CIN * HP * WP2;

    // warp tile: 32(m) x 56(n)
    int warp_m = (wid & 3) * 32;
    int warp_n = (wid >> 2) * 56;

    int amat  = lane >> 3;
    int arow0 = warp_m + (amat & 1) * 8 + (lane & 7);
    int ac16  = amat >> 1;
    int bg    = lane >> 3;
    int bkrow = ((bg & 1) << 3) + (lane & 7);
    int bnx4  = warp_n + ((bg >> 1) << 3);
    int bkrow2 = (((lane >> 3) & 1) << 3) + (lane & 7);

    int kc = tid >> 2;
    int q  = tid & 3;
    int h_local = q >> 1;
    int j0 = (q & 1) * 28;
    int hbase = blockIdx.x * 2;

    float acc[2][7][4];
    #pragma unroll
    for (int t = 0; t < 2; t++)
        #pragma unroll
        for (int nt = 0; nt < 7; nt++)
            #pragma unroll
            for (int i = 0; i < 4; i++) acc[t][nt][i] = 0.f;

    auto loadA = [&](int kt, uint32_t stg_off) {
        int k0 = kt * BK;
        #pragma unroll
        for (int c = 0; c < 4; c++) {
            int idx = c * 256 + tid;
            int row = idx >> 3;
            int c16 = idx & 7;
            size_t src = (size_t)row * KDIM + k0 + c16 * 8;
            cp16(sbase + stg_off + OFF_A + SWADDR(row, c16), A + src);
        }
    };
    auto ldgB = [&](int kt, uint32_t* pf) {
        int k  = kt * BK + kc;
        int ci = k / 9;
        int r9 = k - ci * 9;
        int kh = r9 / 3;
        int kw = r9 - kh * 3;
        const uint32_t* src = Xp + (size_t)(ci * HP + hbase + h_local + kh) * WP2
                                 + (j0 + kw);
        #pragma unroll
        for (int p = 0; p < 14; p++) pf[p] = src[2*p];
    };
    auto stsB = [&](const uint32_t* pf, uint32_t stg_off) {
        uint32_t dst = stg_off + OFF_B + kc * BROWB + (h_local * 56 + j0) * 2;
        #pragma unroll
        for (int p = 0; p < 7; p++)
            *(uint2*)(smem + dst + p * 8) = make_uint2(pf[2*p], pf[2*p+1]);
    };

    {
        uint32_t pf[14];
        loadA(0, 0);
        CP_COMMIT();
        ldgB(0, pf);
        stsB(pf, 0);
    }

    for (int kt = 0; kt < NCHUNK; kt++) {
        uint32_t s_off = (kt & 1) ? STG : 0;
        uint32_t n_off = (kt & 1) ? 0 : STG;
        CP_WAIT0();
        __syncthreads();

        bool hn = (kt + 1) < NCHUNK;
        uint32_t pf[14];
        if (hn) {
            loadA(kt + 1, n_off);
            CP_COMMIT();
            ldgB(kt + 1, pf);
        }

        #pragma unroll
        for (int ks = 0; ks < 4; ks++) {
            uint32_t af[2][4], bf[7][2];
            #pragma unroll
            for (int t = 0; t < 2; t++) {
                uint32_t aoff = SWADDR(arow0 + t*16, ks*2 + ac16);
                ldm_x4(&af[t][0], &af[t][1], &af[t][2], &af[t][3],
                       sbase + s_off + OFF_A + aoff);
            }
            #pragma unroll
            for (int p = 0; p < 3; p++) {
                uint32_t boff = (uint32_t)((ks*16 + bkrow) * BROWB
                                           + (bnx4 + p*16) * 2);
                ldm_x4t(&bf[2*p][0], &bf[2*p][1], &bf[2*p+1][0], &bf[2*p+1][1],
                        sbase + s_off + OFF_B + boff);
            }
            {
                uint32_t boff = (uint32_t)((ks*16 + bkrow2) * BROWB
                                           + (warp_n + 48) * 2);
                ldm_x2t(bf[6], sbase + s_off + OFF_B + boff);
            }
            #pragma unroll
            for (int nt = 0; nt < 7; nt++)
                #pragma unroll
                for (int t = 0; t < 2; t++)
                    mma16816(acc[t][nt], af[t], bf[nt]);
        }

        if (hn) stsB(pf, n_off);
    }

    int r4 = lane >> 2;
    int c2 = (lane & 3) * 2;
    #pragma unroll
    for (int t = 0; t < 2; t++) {
        int or0 = m0 + warp_m + t*16 + r4;
        float bi0 = bias[or0];
        float bi1 = bias[or0 + 8];
        float* op0 = out + ((size_t)b * COUT + or0    ) * HW + n0 + warp_n + c2;
        float* op1 = out + ((size_t)b * COUT + or0 + 8) * HW + n0 + warp_n + c2;
        #pragma unroll
        for (int nt = 0; nt < 7; nt++) {
            float2 v0 = make_float2(acc[t][nt][0] + bi0, acc[t][nt][1] + bi0);
            float2 v1 = make_float2(acc[t][nt][2] + bi1, acc[t][nt][3] + bi1);
            *(float2*)(op0 + nt*8) = v0;
            *(float2*)(op1 + nt*8) = v1;
        }
    }
}

// ---------------- launch ----------------
extern "C" void kernel_launch(void* const* d_in, const int* in_sizes, int n_in,
                              void* d_out, int out_size) {
    const float* x    = (const float*)d_in[0];
    const float* bk   = (const float*)d_in[1];
    const float* bias = (const float*)d_in[2];
    const float* fsw  = (const float*)d_in[3];
    const float* fsb  = (const float*)d_in[4];
    const float* fiw  = (const float*)d_in[5];
    const float* fib  = (const float*)d_in[6];
    const float* fow  = (const float*)d_in[7];
    const float* fob  = (const float*)d_in[8];
    const float* fkw  = (const float*)d_in[9];
    const float* fkb  = (const float*)d_in[10];
    float* out = (float*)d_out;

    k_ctxpad<<<BB*CIN, 256>>>(x);

    int total_warps = BB * (KK + CIN + COUT);
    k_attn<<<(total_warps*32 + 255)/256, 256>>>(fsw, fsb, fiw, fib, fow, fob);

    cudaFuncSetAttribute(k_dyn_mma, cudaFuncAttributeMaxDynamicSharedMemorySize,
                         DYN_SMEM);
    k_dyn_mma<<<(COUT*KDIM)/256, 256, DYN_SMEM>>>(bk, fkw, fkb);

    cudaFuncSetAttribute(k_conv_mma, cudaFuncAttributeMaxDynamicSharedMemorySize,
                         SMEM_BYTES);
    dim3 grid(HW/BN, COUT/BM, BB);   // (28, 2, 16)
    k_conv_mma<<<grid, 256, SMEM_BYTES>>>(bias, out);
}

// round 11
// speedup vs baseline: 1.2833x; 1.0241x over previous
#include <cuda_runtime.h>
#include <cuda_fp16.h>
#include <cstdint>
#include <math.h>

#define BB   16
#define CIN  128
#define COUT 256
#define KK   9
#define HH   56
#define WW   56
#define HW   3136
#define KDIM (CIN*KK)   // 1152
#define HP   58         // padded H
#define WP2  64         // padded/pair row stride (u32 units)

// GEMM tiling (mma.sync fp16 conv path)
#define BM 128
#define BN 112          // 3136 = 28 * 112
#define BK 64
#define NCHUNK (KDIM/BK) // 18

// ---------------- device scratch (no allocations allowed) ----------------
__device__ float g_ctx[BB*CIN];
__device__ float g_attn_sp[BB*KK];
__device__ float g_attn_in[BB*CIN];
__device__ float g_attn_out[BB*COUT];
__device__ __align__(16) __half g_dynA[(size_t)BB*COUT*KDIM];    // 9.4MB fp16
// pair-duplicated padded image: P[pc][hp][w] = (x16(hp,w-1), x16(hp,w))
__device__ __align__(16) uint32_t g_xp2[(size_t)BB*CIN*HP*WP2];  // 30.4MB

// ======================= helpers =====================
__device__ __forceinline__ uint32_t smem_u32(const void* p) {
    uint32_t a;
    asm("{ .reg .u64 t; cvta.to.shared.u64 t, %1; cvt.u32.u64 %0, t; }"
        : "=r"(a) : "l"(p));
    return a;
}
__device__ __forceinline__ void ldm_x4(uint32_t* r0, uint32_t* r1, uint32_t* r2,
                                       uint32_t* r3, uint32_t addr) {
    asm volatile("ldmatrix.sync.aligned.m8n8.x4.shared.b16 {%0,%1,%2,%3}, [%4];"
        : "=r"(*r0), "=r"(*r1), "=r"(*r2), "=r"(*r3) : "r"(addr));
}
__device__ __forceinline__ void ldm_x4t(uint32_t* r0, uint32_t* r1, uint32_t* r2,
                                        uint32_t* r3, uint32_t addr) {
    asm volatile("ldmatrix.sync.aligned.m8n8.x4.trans.shared.b16 {%0,%1,%2,%3}, [%4];"
        : "=r"(*r0), "=r"(*r1), "=r"(*r2), "=r"(*r3) : "r"(addr));
}
__device__ __forceinline__ void ldm_x2t(uint32_t* r, uint32_t addr) {
    asm volatile("ldmatrix.sync.aligned.m8n8.x2.trans.shared.b16 {%0,%1}, [%2];"
        : "=r"(r[0]), "=r"(r[1]) : "r"(addr));
}
__device__ __forceinline__ void mma16816(float* d, const uint32_t* a, const uint32_t* b) {
    asm volatile("mma.sync.aligned.m16n8k16.row.col.f32.f16.f16.f32 "
        "{%0,%1,%2,%3}, {%4,%5,%6,%7}, {%8,%9}, {%0,%1,%2,%3};"
        : "+f"(d[0]), "+f"(d[1]), "+f"(d[2]), "+f"(d[3])
        : "r"(a[0]), "r"(a[1]), "r"(a[2]), "r"(a[3]), "r"(b[0]), "r"(b[1]));
}
__device__ __forceinline__ void cp16(uint32_t dst, const void* src) {
    asm volatile("cp.async.cg.shared.global [%0], [%1], 16;"
        :: "r"(dst), "l"(src));
}
#define CP_COMMIT() asm volatile("cp.async.commit_group;" ::: "memory")
#define CP_WAIT0()  asm volatile("cp.async.wait_group 0;" ::: "memory")

__device__ __forceinline__ uint32_t pack_h2(float lo, float hi) {
    __half2 h = __floats2half2_rn(lo, hi);
    return *reinterpret_cast<uint32_t*>(&h);
}

// 128B-row smem tile, XOR swizzle on 16B columns (conv A tile)
#define SWADDR(row, c16) ((uint32_t)((row) * 128 + (((c16) ^ ((row) & 7)) << 4)))
// 256B-row smem tile, XOR swizzle (k_dyn A/B tiles, 16 c16 units per row)
#define ASW(row, c16) ((uint32_t)((row) * 256 + (((((c16) ^ (row)) & 7) | ((c16) & 8)) << 4)))

// ------- 1) fused: pad + fp16-pair image AND per-channel mean -------------
__global__ __launch_bounds__(256) void k_ctxpad(const float* __restrict__ x) {
    int pc = blockIdx.x;                     // b*CIN + ci
    const float* xc = x + (size_t)pc * HW;
    uint32_t* xp = g_xp2 + (size_t)pc * HP * WP2;
    float s = 0.f;
    for (int idx = threadIdx.x; idx < HP*WP2; idx += 256) {
        int hp = idx >> 6;          // /WP2
        int w  = idx & 63;
        float v0 = 0.f, v1 = 0.f;
        if (hp >= 1 && hp <= HH) {
            const float* row = xc + (hp - 1) * WW;
            if (w >= 1 && w <= WW)     { v0 = row[w - 1]; s += v0; }
            if (w + 1 >= 1 && w + 1 <= WW) v1 = row[w];
        }
        xp[idx] = pack_h2(v0, v1);
    }
    __shared__ float sm[256];
    sm[threadIdx.x] = s; __syncthreads();
    #pragma unroll
    for (int off = 128; off > 0; off >>= 1) {
        if (threadIdx.x < off) sm[threadIdx.x] += sm[threadIdx.x + off];
        __syncthreads();
    }
    if (threadIdx.x == 0) g_ctx[pc] = sm[0] * (1.0f / HW);
}

// ---------------- 2) small attention heads ----------------
__global__ void k_attn(const float* __restrict__ fsw, const float* __restrict__ fsb,
                       const float* __restrict__ fiw, const float* __restrict__ fib,
                       const float* __restrict__ fow, const float* __restrict__ fob) {
    int gw   = (blockIdx.x * blockDim.x + threadIdx.x) >> 5;
    int lane = threadIdx.x & 31;
    const int NS = BB*KK, NI = BB*CIN, NO = BB*COUT;
    if (gw >= NS + NI + NO) return;
    int b; const float* wrow; float bias; float* dst;
    if (gw < NS) {
        b = gw / KK; int r = gw % KK;
        wrow = fsw + r*CIN; bias = fsb[r]; dst = &g_attn_sp[gw];
    } else if (gw < NS + NI) {
        int g = gw - NS; b = g / CIN; int r = g % CIN;
        wrow = fiw + r*CIN; bias = fib[r]; dst = &g_attn_in[g];
    } else {
        int g = gw - NS - NI; b = g / COUT; int r = g % COUT;
        wrow = fow + r*CIN; bias = fob[r]; dst = &g_attn_out[g];
    }
    const float* ctx = g_ctx + b*CIN;
    float s = 0.f;
    #pragma unroll
    for (int j = lane; j < CIN; j += 32) s += ctx[j] * wrow[j];
    #pragma unroll
    for (int o = 16; o > 0; o >>= 1) s += __shfl_down_sync(0xffffffffu, s, o);
    if (lane == 0) *dst = 1.f / (1.f + expf(-(s + bias)));
}

// ------- 3) tensorized big-GEMM + sigmoid + 5-way multiply ----------------
// Phase 1: logits[256 r x 16 b] = fkw_tile[256x128] @ ctx^T  via mma.sync
// Phase 2: smem-transposed epilogue, fully coalesced loads/stores.
// smem: A fp16 [256][128] sw (64KB; logits [16][264]f overlap after MMA)
//       | ctx fp16 (4KB) | attn_in (8KB) | attn_sp (576B) | attn_out (128B)
#define DYN_OFF_CTXB   65536
#define DYN_OFF_AIN    69632
#define DYN_OFF_SP     77824
#define DYN_OFF_AOUT   78400
#define DYN_SMEM       78592
#define LROW           264     // logits row stride in floats

__global__ __launch_bounds__(256) void k_dyn_mma(const float* __restrict__ base_kernel,
                                                 const float* __restrict__ fkw,
                                                 const float* __restrict__ fkb) {
    extern __shared__ char dsm[];
    uint32_t sbase = smem_u32(dsm);
    int tid  = threadIdx.x;
    int wid  = tid >> 5;
    int lane = tid & 31;
    int r0   = blockIdx.x * 256;
    int o0   = r0 / KDIM;

    float* attn_in_s = (float*)(dsm + DYN_OFF_AIN);
    float* attn_sp_s = (float*)(dsm + DYN_OFF_SP);
    float* attn_out_s = (float*)(dsm + DYN_OFF_AOUT);
    float* logit_s = (float*)dsm;

    // ---- preload attn tables (overlaps with fkw staging) ----
    {
        int o1 = min(o0 + 1, COUT - 1);
        if (tid < 32) {
            int b = tid & 15;
            attn_out_s[b*2 + (tid >> 4)] = g_attn_out[b*COUT + ((tid >> 4) ? o1 : o0)];
        }
        if (tid >= 64 && tid < 64 + 144) {
            int t = tid - 64;
            attn_sp_s[t] = g_attn_sp[t];
        }
        #pragma unroll
        for (int i = 0; i < 2; i++) {
            int idx = i * 256 + tid;          // 0..511 -> float4 units of 2048
            *(float4*)(attn_in_s + idx * 4) = *(const float4*)(g_attn_in + idx * 4);
        }
    }

    // ---- stage A: fkw fp32 -> fp16 swizzled smem (coalesced LDG.128 x2) ----
    #pragma unroll
    for (int i = 0; i < 16; i++) {
        int idx = i * 256 + tid;          // 0..4095
        int row = idx >> 4;               // 0..255
        int c16 = idx & 15;               // 16B unit (8 halves)
        const float* src = fkw + (size_t)(r0 + row) * CIN + c16 * 8;
        float4 a = *(const float4*)src;
        float4 b = *(const float4*)(src + 4);
        uint4 u;
        u.x = pack_h2(a.x, a.y); u.y = pack_h2(a.z, a.w);
        u.z = pack_h2(b.x, b.y); u.w = pack_h2(b.z, b.w);
        *(uint4*)(dsm + ASW(row, c16)) = u;
    }
    // ---- stage B: ctx fp32 -> fp16 swizzled smem ----
    {
        int n   = tid >> 4;               // 0..15
        int c16 = tid & 15;
        const float* src = g_ctx + n * CIN + c16 * 8;
        float4 a = *(const float4*)src;
        float4 b = *(const float4*)(src + 4);
        uint4 u;
        u.x = pack_h2(a.x, a.y); u.y = pack_h2(a.z, a.w);
        u.z = pack_h2(b.x, b.y); u.w = pack_h2(b.z, b.w);
        *(uint4*)(dsm + DYN_OFF_CTXB + ASW(n, c16)) = u;
    }
    __syncthreads();

    // ---- MMA: warp handles 32 rows (2 m16 tiles) x 16 b ----
    int warp_m = wid * 32;
    int amat   = lane >> 3;
    int arow0  = warp_m + (amat & 1) * 8 + (lane & 7);
    int ac16   = amat >> 1;
    int brow   = ((lane >> 4) << 3) + (lane & 7);   // 0..15
    int bhalf  = (lane >> 3) & 1;

    float acc[2][2][4];
    #pragma unroll
    for (int t = 0; t < 2; t++)
        #pragma unroll
        for (int nf = 0; nf < 2; nf++)
            #pragma unroll
            for (int e = 0; e < 4; e++) acc[t][nf][e] = 0.f;

    #pragma unroll
    for (int ks = 0; ks < 8; ks++) {
        uint32_t af[2][4], bf[2][2];
        #pragma unroll
        for (int t = 0; t < 2; t++)
            ldm_x4(&af[t][0], &af[t][1], &af[t][2], &af[t][3],
                   sbase + ASW(arow0 + t*16, ks*2 + ac16));
        ldm_x4(&bf[0][0], &bf[0][1], &bf[1][0], &bf[1][1],
               sbase + DYN_OFF_CTXB + ASW(brow, ks*2 + bhalf));
        #pragma unroll
        for (int t = 0; t < 2; t++)
            #pragma unroll
            for (int nf = 0; nf < 2; nf++)
                mma16816(acc[t][nf], af[t], bf[nf]);
    }

    // ---- logits -> smem (A region reusable after all ldmatrix done) ----
    __syncthreads();
    {
        int r4 = lane >> 2;
        int c2 = (lane & 3) * 2;
        #pragma unroll
        for (int t = 0; t < 2; t++)
            #pragma unroll
            for (int nf = 0; nf < 2; nf++)
                #pragma unroll
                for (int e = 0; e < 4; e++) {
                    int rh  = e >> 1, par = e & 1;
                    int b   = nf*8 + c2 + par;
                    int rl  = warp_m + t*16 + rh*8 + r4;
                    logit_s[b * LROW + rl] = acc[t][nf][e];
                }
    }
    __syncthreads();

    // ---- phase 2: transposed coalesced epilogue ----
    {
        int b  = tid >> 4;            // 0..15
        int rg = tid & 15;            // 0..15
        int rl = rg * 16;
        int rr = r0 + rl;

        float bkv[16], fbv[16], zz[16];
        #pragma unroll
        for (int j = 0; j < 16; j += 4) {
            *(float4*)(bkv + j) = *(const float4*)(base_kernel + rr + j);
            *(float4*)(fbv + j) = *(const float4*)(fkb + rr + j);
            *(float4*)(zz + j)  = *(const float4*)(logit_s + b * LROW + rl + j);
        }

        int o   = rr / KDIM;
        int rem = rr - o * KDIM;
        int i   = rem / KK;
        int kk  = rem - i * KK;
        int oi  = o - o0;
        const float* ain = attn_in_s + b * CIN;
        const float* asp = attn_sp_s + b * KK;
        const float* aou = attn_out_s + b * 2;

        __half hv[16];
        #pragma unroll
        for (int j = 0; j < 16; j++) {
            float sg = 1.f / (1.f + expf(-(zz[j] + fbv[j])));
            float v  = bkv[j] * aou[oi] * ain[i] * asp[kk] * sg;
            hv[j] = __float2half_rn(v);
            if (++kk == KK) { kk = 0; if (++i == CIN) { i = 0; oi++; } }
        }
        __half* dst = g_dynA + (size_t)b * COUT * KDIM + rr;
        *(uint4*)dst       = *(uint4*)hv;
        *(uint4*)(dst + 8) = *(uint4*)(hv + 8);
    }
}

// ---- 4) tensor-core conv (R8 config): 8 warps, warp 32x56, K-major B -----
#define OFF_A    0
#define OFF_B    16384
#define BROWB    240
#define STG      31744
#define SMEM_BYTES (2*STG)   // 63488

__global__ __launch_bounds__(256, 2) void k_conv_mma(const float* __restrict__ bias,
                                                     float* __restrict__ out) {
    extern __shared__ char smem[];
    uint32_t sbase = smem_u32(smem);
    int tid  = threadIdx.x;
    int wid  = tid >> 5;
    int lane = tid & 31;

    int b  = blockIdx.z;
    int m0 = blockIdx.y * BM;
    int n0 = blockIdx.x * BN;

    const __half* A = g_dynA + (size_t)(b*COUT + m0) * KDIM;
    const uint32_t* Xp = g_xp2 + (size_t)b * CIN * HP * WP2;

    // warp tile: 32(m) x 56(n)
    int warp_m = (wid & 3) * 32;
    int warp_n = (wid >> 2) * 56;

    int amat  = lane >> 3;
    int arow0 = warp_m + (amat & 1) * 8 + (lane & 7);
    int ac16  = amat >> 1;
    int bg    = lane >> 3;
    int bkrow = ((bg & 1) << 3) + (lane & 7);
    int bnx4  = warp_n + ((bg >> 1) << 3);
    int bkrow2 = (((lane >> 3) & 1) << 3) + (lane & 7);

    int kc = tid >> 2;
    int q  = tid & 3;
    int h_local = q >> 1;
    int j0 = (q & 1) * 28;
    int hbase = blockIdx.x * 2;

    float acc[2][7][4];
    #pragma unroll
    for (int t = 0; t < 2; t++)
        #pragma unroll
        for (int nt = 0; nt < 7; nt++)
            #pragma unroll
            for (int i = 0; i < 4; i++) acc[t][nt][i] = 0.f;

    auto loadA = [&](int kt, uint32_t stg_off) {
        int k0 = kt * BK;
        #pragma unroll
        for (int c = 0; c < 4; c++) {
            int idx = c * 256 + tid;
            int row = idx >> 3;
            int c16 = idx & 7;
            size_t src = (size_t)row * KDIM + k0 + c16 * 8;
            cp16(sbase + stg_off + OFF_A + SWADDR(row, c16), A + src);
        }
    };
    auto ldgB = [&](int kt, uint32_t* pf) {
        int k  = kt * BK + kc;
        int ci = k / 9;
        int r9 = k - ci * 9;
        int kh = r9 / 3;
        int kw = r9 - kh * 3;
        const uint32_t* src = Xp + (size_t)(ci * HP + hbase + h_local + kh) * WP2
                                 + (j0 + kw);
        #pragma unroll
        for (int p = 0; p < 14; p++) pf[p] = src[2*p];
    };
    auto stsB = [&](const uint32_t* pf, uint32_t stg_off) {
        uint32_t dst = stg_off + OFF_B + kc * BROWB + (h_local * 56 + j0) * 2;
        #pragma unroll
        for (int p = 0; p < 7; p++)
            *(uint2*)(smem + dst + p * 8) = make_uint2(pf[2*p], pf[2*p+1]);
    };

    {
        uint32_t pf[14];
        loadA(0, 0);
        CP_COMMIT();
        ldgB(0, pf);
        stsB(pf, 0);
    }

    for (int kt = 0; kt < NCHUNK; kt++) {
        uint32_t s_off = (kt & 1) ? STG : 0;
        uint32_t n_off = (kt & 1) ? 0 : STG;
        CP_WAIT0();
        __syncthreads();

        bool hn = (kt + 1) < NCHUNK;
        uint32_t pf[14];
        if (hn) {
            loadA(kt + 1, n_off);
            CP_COMMIT();
            ldgB(kt + 1, pf);
        }

        #pragma unroll
        for (int ks = 0; ks < 4; ks++) {
            uint32_t af[2][4], bf[7][2];
            #pragma unroll
            for (int t = 0; t < 2; t++) {
                uint32_t aoff = SWADDR(arow0 + t*16, ks*2 + ac16);
                ldm_x4(&af[t][0], &af[t][1], &af[t][2], &af[t][3],
                       sbase + s_off + OFF_A + aoff);
            }
            #pragma unroll
            for (int p = 0; p < 3; p++) {
                uint32_t boff = (uint32_t)((ks*16 + bkrow) * BROWB
                                           + (bnx4 + p*16) * 2);
                ldm_x4t(&bf[2*p][0], &bf[2*p][1], &bf[2*p+1][0], &bf[2*p+1][1],
                        sbase + s_off + OFF_B + boff);
            }
            {
                uint32_t boff = (uint32_t)((ks*16 + bkrow2) * BROWB
                                           + (warp_n + 48) * 2);
                ldm_x2t(bf[6], sbase + s_off + OFF_B + boff);
            }
            #pragma unroll
            for (int nt = 0; nt < 7; nt++)
                #pragma unroll
                for (int t = 0; t < 2; t++)
                    mma16816(acc[t][nt], af[t], bf[nt]);
        }

        if (hn) stsB(pf, n_off);
    }

    int r4 = lane >> 2;
    int c2 = (lane & 3) * 2;
    #pragma unroll
    for (int t = 0; t < 2; t++) {
        int or0 = m0 + warp_m + t*16 + r4;
        float bi0 = bias[or0];
        float bi1 = bias[or0 + 8];
        float* op0 = out + ((size_t)b * COUT + or0    ) * HW + n0 + warp_n + c2;
        float* op1 = out + ((size_t)b * COUT + or0 + 8) * HW + n0 + warp_n + c2;
        #pragma unroll
        for (int nt = 0; nt < 7; nt++) {
            float2 v0 = make_float2(acc[t][nt][0] + bi0, acc[t][nt][1] + bi0);
            float2 v1 = make_float2(acc[t][nt][2] + bi1, acc[t][nt][3] + bi1);
            *(float2*)(op0 + nt*8) = v0;
            *(float2*)(op1 + nt*8) = v1;
        }
    }
}

// ---------------- launch ----------------
extern "C" void kernel_launch(void* const* d_in, const int* in_sizes, int n_in,
                              void* d_out, int out_size) {
    const float* x    = (const float*)d_in[0];
    const float* bk   = (const float*)d_in[1];
    const float* bias = (const float*)d_in[2];
    const float* fsw  = (const float*)d_in[3];
    const float* fsb  = (const float*)d_in[4];
    const float* fiw  = (const float*)d_in[5];
    const float* fib  = (const float*)d_in[6];
    const float* fow  = (const float*)d_in[7];
    const float* fob  = (const float*)d_in[8];
    const float* fkw  = (const float*)d_in[9];
    const float* fkb  = (const float*)d_in[10];
    float* out = (float*)d_out;

    k_ctxpad<<<BB*CIN, 256>>>(x);

    int total_warps = BB * (KK + CIN + COUT);
    k_attn<<<(total_warps*32 + 255)/256, 256>>>(fsw, fsb, fiw, fib, fow, fob);

    cudaFuncSetAttribute(k_dyn_mma, cudaFuncAttributeMaxDynamicSharedMemorySize,
                         DYN_SMEM);
    k_dyn_mma<<<(COUT*KDIM)/256, 256, DYN_SMEM>>>(bk, fkw, fkb);

    cudaFuncSetAttribute(k_conv_mma, cudaFuncAttributeMaxDynamicSharedMemorySize,
                         SMEM_BYTES);
    dim3 grid(HW/BN, COUT/BM, BB);   // (28, 2, 16)
    k_conv_mma<<<grid, 256, SMEM_BYTES>>>(bias, out);
}